// round 15
// baseline (speedup 1.0000x reference)
#include <cuda_runtime.h>
#include <cstdint>

// Problem constants: N=200000 nodes, D=256 features, G=512 graphs.
#define D 256
#define G 512
#define GPB 8                  // graphs per block-tile in GEMM
#define KPB 32                 // k-values per block-slice in GEMM
#define RPB 128                // rows per block in segsum

// g_sum invariant: zero at module load; the GEMM re-zeroes every element it
// consumes, so every kernel_launch execution starts with g_sum == 0 without
// a dedicated init kernel.
__device__ int   g_layout;         // 0 = int32 indices, 1 = int64 indices
__device__ float g_sum[G * D];     // pooled features (self-resetting)
__device__ float g_acc[G * D];     // bias-seeded split-K accumulator -> sum@W + b

__device__ __forceinline__ int load_idx(const int* __restrict__ raw, int i, int layout)
{
    return layout ? raw[2 * i] : raw[i];
}

// ---------------------------------------------------------------------------
// Kernel 1: segment sum, MLP-batched. __launch_bounds__(256,5) caps regs at
// 51 (was 60) -> 5 CTAs/SM (occ 43.5% -> ~62.5%), +25% in-flight loads on a
// DRAM-latency-exposed kernel. Inner loop is branchless: OOB rows carry
// sidx=-1 and v=0, so they flush the live accumulator and then harmlessly
// accumulate zeros into segment -1 (never flushed).
// Folded duties: per-block layout detection from the sorted index tail;
// first G blocks seed g_acc with the bias.
// ---------------------------------------------------------------------------
__global__ void __launch_bounds__(256, 5) k_segsum(const float* __restrict__ h,
                                                   const int* __restrict__ raw,
                                                   const float* __restrict__ b, int n)
{
    // layout detection (per-block; all blocks read the same 1 KB tail -> L2)
    int w = n - 256 + (int)threadIdx.x;      // n >= 256
    int vv = (w >= 0) ? raw[w] : 0;
    int odd_nz  = (vv != 0 &&  (w & 1)) ? 1 : 0;
    int even_nz = (vv != 0 && !(w & 1)) ? 1 : 0;
    int o = __syncthreads_or(odd_nz);
    int e = __syncthreads_or(even_nz);
    int layout = o ? 0 : (e ? 1 : 0);
    if (blockIdx.x == 0 && threadIdx.x == 0)
        g_layout = layout;

    // side job: seed g_acc = bias (g_acc[i] = b[i % D])
    if (blockIdx.x < G) {
        float bv = b[threadIdx.x];
        int base = blockIdx.x * 512 + threadIdx.x;
        g_acc[base]       = bv;
        g_acc[base + 256] = bv;
    }

    __shared__ int sidx[RPB];
    int r0 = blockIdx.x * RPB;
    if (threadIdx.x < RPB) {
        int r = r0 + threadIdx.x;
        sidx[threadIdx.x] = (r < n) ? load_idx(raw, r, layout) : -1;
    }
    __syncthreads();

    int tx = threadIdx.x & 63;
    int ty = threadIdx.x >> 6;

    float4 acc = make_float4(0.f, 0.f, 0.f, 0.f);
    int cur = -1;

#pragma unroll
    for (int base = 0; base < RPB; base += 32) {
        float4 v[8];
#pragma unroll
        for (int j = 0; j < 8; j++) {
            int row = r0 + base + ty + j * 4;
            if (row < n)
                v[j] = *reinterpret_cast<const float4*>(h + (size_t)row * D + tx * 4);
            else
                v[j] = make_float4(0.f, 0.f, 0.f, 0.f);
        }
#pragma unroll
        for (int j = 0; j < 8; j++) {
            int seg = sidx[base + ty + j * 4];   // -1 for OOB rows
            if (seg != cur) {
                if (cur >= 0) {
                    float* dst = &g_sum[cur * D + tx * 4];
                    atomicAdd(dst + 0, acc.x);
                    atomicAdd(dst + 1, acc.y);
                    atomicAdd(dst + 2, acc.z);
                    atomicAdd(dst + 3, acc.w);
                }
                acc = make_float4(0.f, 0.f, 0.f, 0.f);
                cur = seg;
            }
            acc.x += v[j].x; acc.y += v[j].y; acc.z += v[j].z; acc.w += v[j].w;
        }
    }
    if (cur >= 0) {
        float* dst = &g_sum[cur * D + tx * 4];
        atomicAdd(dst + 0, acc.x);
        atomicAdd(dst + 1, acc.y);
        atomicAdd(dst + 2, acc.z);
        atomicAdd(dst + 3, acc.w);
    }
}

// ---------------------------------------------------------------------------
// Kernel 2: split-K GEMM. grid (G/GPB, D/KPB) = (64, 8) = 512 blocks;
// thread t owns column t for 8 graphs over 32 k's; flush via smem transpose
// + red.global.add.v4.f32. SELF-RESET: each g_sum element is read by
// exactly one block, which writes 0 back (zero-invariant for next replay).
// ---------------------------------------------------------------------------
__global__ void __launch_bounds__(256) k_gemm_splitk(const float* __restrict__ W)
{
    __shared__ float s[GPB][KPB];
    __shared__ float s2[GPB][D];
    int g0 = blockIdx.x * GPB;
    int k0 = blockIdx.y * KPB;
    int t  = threadIdx.x;

    float w[KPB];
#pragma unroll
    for (int kk = 0; kk < KPB; kk++)
        w[kk] = __ldg(&W[(k0 + kk) * D + t]);

    {
        int si = (g0 + (t >> 5)) * D + (k0 + (t & 31));
        s[t >> 5][t & 31] = g_sum[si];
        g_sum[si] = 0.0f;            // restore zero-invariant
    }
    __syncthreads();

    float acc[GPB];
#pragma unroll
    for (int r = 0; r < GPB; r++) acc[r] = 0.0f;

#pragma unroll
    for (int kk = 0; kk < KPB; kk++) {
#pragma unroll
        for (int r = 0; r < GPB; r++)
            acc[r] = fmaf(s[r][kk], w[kk], acc[r]);
    }

#pragma unroll
    for (int r = 0; r < GPB; r++)
        s2[r][t] = acc[r];
    __syncthreads();

    int q  = t & 63;
    int gb = t >> 6;
#pragma unroll
    for (int j = 0; j < 2; j++) {
        int r = gb + j * 4;
        float4 v = *reinterpret_cast<float4*>(&s2[r][q * 4]);
        float* dst = &g_acc[(g0 + r) * D + q * 4];
        asm volatile("red.global.add.v4.f32 [%0], {%1, %2, %3, %4};"
                     :: "l"(dst), "f"(v.x), "f"(v.y), "f"(v.z), "f"(v.w)
                     : "memory");
    }
}

// ---------------------------------------------------------------------------
// Kernel 3: out = relu(g_acc[seg]) + h — lean 2-quad form (measured at its
// traffic floor). Reverse row order harvests the L2 tail left by k_segsum;
// misses evict-first. Frozen.
// ---------------------------------------------------------------------------
__global__ void k_out(const float* __restrict__ h, const int* __restrict__ raw,
                      float* __restrict__ out, int n)
{
    int layout = g_layout;
    int gt = blockIdx.x * blockDim.x + threadIdx.x;   // one thread per 2 quads
    int ridx = gt >> 5;
    if (ridx >= n) return;
    int i = n - 1 - ridx;     // reverse row order
    int q = (gt & 31) * 2;
    int seg = load_idx(raw, i, layout);

    const float4* hp = reinterpret_cast<const float4*>(h + (size_t)i * D) + q;
    const float4 a0 = __ldcs(hp);
    const float4 a1 = __ldcs(hp + 1);
    const float4* vp = reinterpret_cast<const float4*>(g_acc + seg * D) + q;
    const float4 v0 = vp[0];
    const float4 v1 = vp[1];

    float4 r0, r1;
    r0.x = fmaxf(v0.x, 0.0f) + a0.x;  r0.y = fmaxf(v0.y, 0.0f) + a0.y;
    r0.z = fmaxf(v0.z, 0.0f) + a0.z;  r0.w = fmaxf(v0.w, 0.0f) + a0.w;
    r1.x = fmaxf(v1.x, 0.0f) + a1.x;  r1.y = fmaxf(v1.y, 0.0f) + a1.y;
    r1.z = fmaxf(v1.z, 0.0f) + a1.z;  r1.w = fmaxf(v1.w, 0.0f) + a1.w;

    float4* op = reinterpret_cast<float4*>(out + (size_t)i * D) + q;
    __stcs(op, r0);
    __stcs(op + 1, r1);
}

extern "C" void kernel_launch(void* const* d_in, const int* in_sizes, int n_in,
                              void* d_out, int out_size)
{
    const float* h   = (const float*)d_in[0];
    const int*   raw = (const int*)  d_in[1];
    const float* W   = (const float*)d_in[2];
    const float* b   = (const float*)d_in[3];
    float* out = (float*)d_out;

    const int n  = in_sizes[1];
    const int nbs = (n + RPB - 1) / RPB;

    k_segsum<<<nbs, 256>>>(h, raw, b, n);
    k_gemm_splitk<<<dim3(G / GPB, D / KPB), 256>>>(W);
    {
        long long tt = (long long)n * 32;   // one thread per 2 float4
        int blocks = (int)((tt + 255) / 256);
        k_out<<<blocks, 256>>>(h, raw, out, n);
    }
}

// round 16
// speedup vs baseline: 1.0042x; 1.0042x over previous
#include <cuda_runtime.h>
#include <cstdint>

// Problem constants: N=200000 nodes, D=256 features, G=512 graphs.
#define D 256
#define G 512
#define GPB 8                  // graphs per block-tile in GEMM
#define KPB 32                 // k-values per block-slice in GEMM
#define RPB 128                // rows per block in segsum

// g_sum invariant: zero at module load; the GEMM re-zeroes every element it
// consumes, so every kernel_launch execution starts with g_sum == 0 without
// a dedicated init kernel.
__device__ int   g_layout;         // 0 = int32 indices, 1 = int64 indices
__device__ float g_sum[G * D];     // pooled features (self-resetting)
__device__ float g_acc[G * D];     // bias-seeded split-K accumulator -> sum@W + b

__device__ __forceinline__ int load_idx(const int* __restrict__ raw, int i, int layout)
{
    return layout ? raw[2 * i] : raw[i];
}

// ---------------------------------------------------------------------------
// Kernel 1: segment sum over sorted batch_idx, MLP-batched (at the ~5.5TB/s
// achievable streaming ceiling). Block owns RPB=128 contiguous rows; 64
// column-quads x 4 row-stripes; chunks of 8 rows batch 8 independent float4
// loads, then branchless segment logic on registers (OOB rows carry
// sidx=-1, v=0: they flush the live accumulator and accumulate zeros into
// segment -1, never flushed). Atomic flush only on segment boundaries.
// Folded duties (hidden under the 205 MB stream):
//  - per-block layout detection from the LAST 256 int32 words of the sorted
//    index buffer (int32 => odd words nonzero; int64 (<2^32) => odd zero,
//    even nonzero; all-zero => either path correct); block 0 publishes.
//  - first G blocks seed g_acc with the bias (consumed by the GEMM).
// Evict-normal h loads leave the tail of h in L2 for k_out's reverse pass.
// ---------------------------------------------------------------------------
__global__ void __launch_bounds__(256) k_segsum(const float* __restrict__ h,
                                                const int* __restrict__ raw,
                                                const float* __restrict__ b, int n)
{
    // layout detection (per-block; all blocks read the same 1 KB tail -> L2)
    int w = n - 256 + (int)threadIdx.x;      // n >= 256
    int vv = (w >= 0) ? raw[w] : 0;
    int odd_nz  = (vv != 0 &&  (w & 1)) ? 1 : 0;
    int even_nz = (vv != 0 && !(w & 1)) ? 1 : 0;
    int o = __syncthreads_or(odd_nz);
    int e = __syncthreads_or(even_nz);
    int layout = o ? 0 : (e ? 1 : 0);
    if (blockIdx.x == 0 && threadIdx.x == 0)
        g_layout = layout;

    // side job: seed g_acc = bias (g_acc[i] = b[i % D])
    if (blockIdx.x < G) {
        float bv = b[threadIdx.x];
        int base = blockIdx.x * 512 + threadIdx.x;
        g_acc[base]       = bv;
        g_acc[base + 256] = bv;
    }

    __shared__ int sidx[RPB];
    int r0 = blockIdx.x * RPB;
    if (threadIdx.x < RPB) {
        int r = r0 + threadIdx.x;
        sidx[threadIdx.x] = (r < n) ? load_idx(raw, r, layout) : -1;
    }
    __syncthreads();

    int tx = threadIdx.x & 63;
    int ty = threadIdx.x >> 6;

    float4 acc = make_float4(0.f, 0.f, 0.f, 0.f);
    int cur = -1;

#pragma unroll
    for (int base = 0; base < RPB; base += 32) {
        float4 v[8];
#pragma unroll
        for (int j = 0; j < 8; j++) {
            int row = r0 + base + ty + j * 4;
            if (row < n)
                v[j] = *reinterpret_cast<const float4*>(h + (size_t)row * D + tx * 4);
            else
                v[j] = make_float4(0.f, 0.f, 0.f, 0.f);
        }
#pragma unroll
        for (int j = 0; j < 8; j++) {
            int seg = sidx[base + ty + j * 4];   // -1 for OOB rows
            if (seg != cur) {
                if (cur >= 0) {
                    float* dst = &g_sum[cur * D + tx * 4];
                    atomicAdd(dst + 0, acc.x);
                    atomicAdd(dst + 1, acc.y);
                    atomicAdd(dst + 2, acc.z);
                    atomicAdd(dst + 3, acc.w);
                }
                acc = make_float4(0.f, 0.f, 0.f, 0.f);
                cur = seg;
            }
            acc.x += v[j].x; acc.y += v[j].y; acc.z += v[j].z; acc.w += v[j].w;
        }
    }
    if (cur >= 0) {
        float* dst = &g_sum[cur * D + tx * 4];
        atomicAdd(dst + 0, acc.x);
        atomicAdd(dst + 1, acc.y);
        atomicAdd(dst + 2, acc.z);
        atomicAdd(dst + 3, acc.w);
    }
}

// ---------------------------------------------------------------------------
// Kernel 2: split-K GEMM (~5us). grid (G/GPB, D/KPB) = (64, 8) = 512
// blocks; thread t owns column t for 8 graphs over 32 k's; flush via smem
// transpose + red.global.add.v4.f32 (2 vector reds/thread — atomic lane
// count was the binding constraint of the scalar version).
// SELF-RESET: each g_sum element is read by exactly one block (the grid
// perfectly partitions G*D); that block writes 0 back, restoring the
// zero-invariant for the next graph replay (replaces the init kernel).
// ---------------------------------------------------------------------------
__global__ void __launch_bounds__(256) k_gemm_splitk(const float* __restrict__ W)
{
    __shared__ float s[GPB][KPB];
    __shared__ float s2[GPB][D];
    int g0 = blockIdx.x * GPB;
    int k0 = blockIdx.y * KPB;
    int t  = threadIdx.x;

    float w[KPB];
#pragma unroll
    for (int kk = 0; kk < KPB; kk++)
        w[kk] = __ldg(&W[(k0 + kk) * D + t]);

    {
        int si = (g0 + (t >> 5)) * D + (k0 + (t & 31));
        s[t >> 5][t & 31] = g_sum[si];
        g_sum[si] = 0.0f;            // restore zero-invariant
    }
    __syncthreads();

    float acc[GPB];
#pragma unroll
    for (int r = 0; r < GPB; r++) acc[r] = 0.0f;

#pragma unroll
    for (int kk = 0; kk < KPB; kk++) {
#pragma unroll
        for (int r = 0; r < GPB; r++)
            acc[r] = fmaf(s[r][kk], w[kk], acc[r]);
    }

#pragma unroll
    for (int r = 0; r < GPB; r++)
        s2[r][t] = acc[r];
    __syncthreads();

    int q  = t & 63;
    int gb = t >> 6;
#pragma unroll
    for (int j = 0; j < 2; j++) {
        int r = gb + j * 4;
        float4 v = *reinterpret_cast<float4*>(&s2[r][q * 4]);
        float* dst = &g_acc[(g0 + r) * D + q * 4];
        asm volatile("red.global.add.v4.f32 [%0], {%1, %2, %3, %4};"
                     :: "l"(dst), "f"(v.x), "f"(v.y), "f"(v.z), "f"(v.w)
                     : "memory");
    }
}

// ---------------------------------------------------------------------------
// Kernel 3: out = relu(g_acc[seg]) + h — lean 2-quad form (at its traffic
// floor; ~6.5TB/s effective via L2 harvest). Reverse row order harvests
// the tail of h left in L2 by k_segsum; misses and stores evict-first.
// ---------------------------------------------------------------------------
__global__ void k_out(const float* __restrict__ h, const int* __restrict__ raw,
                      float* __restrict__ out, int n)
{
    int layout = g_layout;
    int gt = blockIdx.x * blockDim.x + threadIdx.x;   // one thread per 2 quads
    int ridx = gt >> 5;
    if (ridx >= n) return;
    int i = n - 1 - ridx;     // reverse row order
    int q = (gt & 31) * 2;
    int seg = load_idx(raw, i, layout);

    const float4* hp = reinterpret_cast<const float4*>(h + (size_t)i * D) + q;
    const float4 a0 = __ldcs(hp);
    const float4 a1 = __ldcs(hp + 1);
    const float4* vp = reinterpret_cast<const float4*>(g_acc + seg * D) + q;
    const float4 v0 = vp[0];
    const float4 v1 = vp[1];

    float4 r0, r1;
    r0.x = fmaxf(v0.x, 0.0f) + a0.x;  r0.y = fmaxf(v0.y, 0.0f) + a0.y;
    r0.z = fmaxf(v0.z, 0.0f) + a0.z;  r0.w = fmaxf(v0.w, 0.0f) + a0.w;
    r1.x = fmaxf(v1.x, 0.0f) + a1.x;  r1.y = fmaxf(v1.y, 0.0f) + a1.y;
    r1.z = fmaxf(v1.z, 0.0f) + a1.z;  r1.w = fmaxf(v1.w, 0.0f) + a1.w;

    float4* op = reinterpret_cast<float4*>(out + (size_t)i * D) + q;
    __stcs(op, r0);
    __stcs(op + 1, r1);
}

extern "C" void kernel_launch(void* const* d_in, const int* in_sizes, int n_in,
                              void* d_out, int out_size)
{
    const float* h   = (const float*)d_in[0];
    const int*   raw = (const int*)  d_in[1];
    const float* W   = (const float*)d_in[2];
    const float* b   = (const float*)d_in[3];
    float* out = (float*)d_out;

    const int n  = in_sizes[1];
    const int nbs = (n + RPB - 1) / RPB;

    k_segsum<<<nbs, 256>>>(h, raw, b, n);
    k_gemm_splitk<<<dim3(G / GPB, D / KPB), 256>>>(W);
    {
        long long tt = (long long)n * 32;   // one thread per 2 float4
        int blocks = (int)((tt + 255) / 256);
        k_out<<<blocks, 256>>>(h, raw, out, n);
    }
}